// round 16
// baseline (speedup 1.0000x reference)
#include <cuda_runtime.h>
#include <math_constants.h>
#include <cstdint>

#define H    32
#define T    8192
#define KQ   16
#define D    128
#define NC   64          // chunks per head
#define CS   128         // keys per chunk
#define ST   64          // subtile rows held in smem
#define NSUB (CS/ST)
#define TPB  256
#define TSTR 132         // tile row stride (floats)
#define XSTR 133         // suffix row stride (floats)
#define SSTR 68          // score row stride

#define PI_F     3.14159274101257324f   // 0x40490FDB
#define TWO_PI_F 6.28318548202514648f   // 0x40C90FDB

// dynamic smem layout (floats)
#define OFF_Q    0
#define OFF_TILE (OFF_Q + KQ*D)
#define OFF_SFX  (OFF_TILE + ST*TSTR)
#define OFF_S    (OFF_SFX + ST*XSTR)
#define SMEM_FLOATS (OFF_S + KQ*SSTR)
#define SMEM_BYTES  (SMEM_FLOATS*4)

// ---- split-softmax partials ----
__device__ float g_pm[H*NC*KQ];
__device__ float g_pl[H*NC*KQ];
__device__ float g_po[(size_t)H*NC*KQ*D];

// ---- reference-exact quantization tables (filled by init_kernel) ----
__device__ float  d_Tmid[8];
__device__ float  d_Tpos[8];
__device__ float  d_Tneg[8];
__device__ float2 d_lutM[8];
__device__ float2 d_lutL[8];

// Reference acos: StableHLO functional_algorithms real-acos decomposition,
//   acos(x) = atan2(sqrt(fl((1-x))*fl((1+x))), x)
// with f32 IEEE intermediates and a CORRECTLY-ROUNDED f32 atan2 (emulated by
// double atan2 of the exact f32 args, then rounding once) — matching CPU-XLA
// (glibc atan2f). No x==-1 special case needed: atan2(0,-1) = pi.
__device__ __forceinline__ float ref_theta(float c) {
    float a = __fsub_rn(1.0f, c);
    float b = __fadd_rn(1.0f, c);
    float s = __fsqrt_rn(__fmul_rn(a, b));
    return (float)atan2((double)s, (double)c);
}
__device__ __forceinline__ int F_mid(float c) {
    return (int)rintf(__fmul_rn(__fdiv_rn(ref_theta(c), PI_F), 7.0f));
}
__device__ __forceinline__ int F_last(float c, bool neg) {
    float th = ref_theta(c);
    if (neg) th = __fsub_rn(TWO_PI_F, th);
    return (int)rintf(__fmul_rn(__fdiv_rn(th, TWO_PI_F), 7.0f));
}
__device__ __forceinline__ unsigned f2key(float f) {
    unsigned u = __float_as_uint(f);
    return (u & 0x80000000u) ? ~u : (u | 0x80000000u);
}
__device__ __forceinline__ float key2f(unsigned k) {
    return __uint_as_float((k & 0x80000000u) ? (k ^ 0x80000000u) : ~k);
}

__global__ void init_kernel() {
    if (threadIdx.x != 0 || blockIdx.x != 0) return;
    const unsigned KLO = f2key(-1.0f), KHI = f2key(1.0f);
    for (int k = 1; k <= 7; k++) {          // F_mid decreasing: F(-1)=7, F(1)=0
        unsigned lo = KLO, hi = KHI;
        while (hi - lo > 1u) {
            unsigned mid = lo + (hi - lo) / 2u;
            if (F_mid(key2f(mid)) >= k) lo = mid; else hi = mid;
        }
        d_Tmid[k] = key2f(lo);
    }
    for (int k = 1; k <= 4; k++) {          // F_last(+) decreasing: 4 -> 0
        unsigned lo = KLO, hi = KHI;
        while (hi - lo > 1u) {
            unsigned mid = lo + (hi - lo) / 2u;
            if (F_last(key2f(mid), false) >= k) lo = mid; else hi = mid;
        }
        d_Tpos[k] = key2f(lo);
    }
    for (int k = 5; k <= 7; k++) {          // F_last(-) increasing: 4 -> 7
        unsigned lo = KLO, hi = KHI;
        while (hi - lo > 1u) {
            unsigned mid = lo + (hi - lo) / 2u;
            if (F_last(key2f(mid), true) >= k) hi = mid; else lo = mid;
        }
        d_Tneg[k] = key2f(hi);
    }
    // dequant LUTs: theta = fl(fl(j/7)*range); sin/cos correctly rounded
    for (int j = 0; j < 8; j++) {
        float tM = __fmul_rn(__fdiv_rn((float)j, 7.0f), PI_F);
        d_lutM[j] = make_float2((float)sin((double)tM), (float)cos((double)tM));
        float tL = __fmul_rn(__fdiv_rn((float)j, 7.0f), TWO_PI_F);
        d_lutL[j] = make_float2((float)sin((double)tL), (float)cos((double)tL));
    }
}

// thread-per-row polar roundtrip, bit-matching the reference (CPU-XLA):
// sequential tail-first f32 cumsum, IEEE sqrt/div, bisected bin thresholds.
__device__ __forceinline__ void polar_tile_exact(const float* __restrict__ src,
                                                 float* __restrict__ tile,
                                                 float* __restrict__ sfx,
                                                 const float* __restrict__ tm,
                                                 const float* __restrict__ tp,
                                                 const float* __restrict__ tn,
                                                 const float2* __restrict__ lm,
                                                 const float2* __restrict__ ll,
                                                 int tid)
{
    for (int i = tid; i < ST*32; i += TPB) {
        int row = i >> 5, col = i & 31;
        reinterpret_cast<float4*>(tile + row*TSTR)[col] =
            reinterpret_cast<const float4*>(src + (size_t)row*D)[col];
    }
    __syncthreads();
    if (tid < ST) {
        float* xr = tile + tid*TSTR;
        float* sr = sfx  + tid*XSTR;
        float s = 0.0f;
        #pragma unroll 4
        for (int i = 127; i >= 0; --i) {
            float x = xr[i];
            s = __fadd_rn(s, __fmul_rn(x, x));
            sr[i] = s;
        }
        const float rn  = __fsqrt_rn(s);
        const bool  neg = (xr[127] < 0.0f);
        float cp = 1.0f;
        #pragma unroll 2
        for (int i = 0; i < 126; ++i) {
            float c = __fdiv_rn(xr[i], fmaxf(__fsqrt_rn(sr[i]), 1e-12f));
            c = fminf(1.0f, fmaxf(-1.0f, c));
            int idx = (int)(c <= tm[1]) + (int)(c <= tm[2]) + (int)(c <= tm[3])
                    + (int)(c <= tm[4]) + (int)(c <= tm[5]) + (int)(c <= tm[6])
                    + (int)(c <= tm[7]);
            float2 sc = lm[idx];
            xr[i] = __fmul_rn(__fmul_rn(rn, cp), sc.y);
            cp    = __fmul_rn(cp, sc.x);
        }
        {   // i = 126: last angle, range 2*pi, sign from x[127]
            float c = __fdiv_rn(xr[126], fmaxf(__fsqrt_rn(sr[126]), 1e-12f));
            c = fminf(1.0f, fmaxf(-1.0f, c));
            int idx;
            if (neg) idx = 4 + (int)(c >= tn[5]) + (int)(c >= tn[6]) + (int)(c >= tn[7]);
            else     idx = (int)(c <= tp[1]) + (int)(c <= tp[2])
                         + (int)(c <= tp[3]) + (int)(c <= tp[4]);
            float2 sc = ll[idx];
            xr[126] = __fmul_rn(__fmul_rn(rn, cp), sc.y);
            cp      = __fmul_rn(cp, sc.x);
        }
        xr[127] = __fmul_rn(rn, cp);
    }
    __syncthreads();
}

__global__ void __launch_bounds__(TPB)
attn_kernel(const float* __restrict__ q_g,
            const float* __restrict__ k_g,
            const float* __restrict__ v_g,
            const float* __restrict__ nz_g)
{
    extern __shared__ float sm[];
    float*  sQ    = sm + OFF_Q;
    float*  sTile = sm + OFF_TILE;
    float*  sSfx  = sm + OFF_SFX;
    float*  sS    = sm + OFF_S;
    __shared__ float  sTm[8], sTp[8], sTn[8];
    __shared__ float2 sLm[8], sLl[8];

    const int chunk = blockIdx.x;
    const int h     = blockIdx.y;
    const int tid   = threadIdx.x;
    const int qi    = tid >> 4, g = tid & 15;
    const float inv_sqrt_d = __fdiv_rn(1.0f, __fsqrt_rn(128.0f));

    if (tid < 8) {
        sTm[tid] = d_Tmid[tid]; sTp[tid] = d_Tpos[tid]; sTn[tid] = d_Tneg[tid];
        sLm[tid] = d_lutM[tid]; sLl[tid] = d_lutL[tid];
    }
    {
        const float4* qh = reinterpret_cast<const float4*>(q_g + (size_t)h*KQ*D);
        #pragma unroll
        for (int i = tid; i < KQ*D/4; i += TPB)
            reinterpret_cast<float4*>(sQ)[i] = qh[i];
    }
    __syncthreads();

    const int t0 = chunk * CS;
    float m_run = -CUDART_INF_F, l_run = 0.0f;
    float4 oA = {0,0,0,0}, oB = {0,0,0,0};

    #pragma unroll 1
    for (int sub = 0; sub < NSUB; ++sub) {
        const int tt = t0 + sub*ST;
        // ---- K polar roundtrip (reference-exact bins) ----
        polar_tile_exact(k_g + ((size_t)h*T + tt)*D, sTile, sSfx,
                         sTm, sTp, sTn, sLm, sLl, tid);
        // ---- scores S[16 x 64] ----
        {
            const int lane = tid & 31, wid = tid >> 5;
            const int key = lane & 7, dg = lane >> 3;
            float acc[KQ];
            #pragma unroll
            for (int i = 0; i < KQ; i++) acc[i] = 0.0f;
            const float* kr = sTile + (wid*8 + key)*TSTR + dg*32;
            const float* qb = sQ + dg*32;
            #pragma unroll
            for (int j = 0; j < 8; j++) {
                float4 kv = reinterpret_cast<const float4*>(kr)[j];
                #pragma unroll
                for (int q = 0; q < KQ; q++) {
                    float4 qv = reinterpret_cast<const float4*>(qb + q*D)[j];
                    acc[q] = fmaf(kv.x, qv.x, fmaf(kv.y, qv.y,
                             fmaf(kv.z, qv.z, fmaf(kv.w, qv.w, acc[q]))));
                }
            }
            #pragma unroll
            for (int q = 0; q < KQ; q++) {
                acc[q] += __shfl_xor_sync(0xffffffffu, acc[q], 8);
                acc[q] += __shfl_xor_sync(0xffffffffu, acc[q], 16);
            }
            #pragma unroll
            for (int qq = 0; qq < 4; qq++) {
                int q = dg*4 + qq;
                sS[q*SSTR + wid*8 + key] = __fmul_rn(acc[q], inv_sqrt_d);
            }
        }
        __syncthreads();
        // ---- online softmax update (adds noise) ----
        {
            float4 sv = *reinterpret_cast<const float4*>(&sS[qi*SSTR + g*4]);
            float4 nz = reinterpret_cast<const float4*>(
                            nz_g + ((size_t)(h*KQ + qi))*T + tt)[g];
            float a0 = sv.x + nz.x, a1 = sv.y + nz.y;
            float a2 = sv.z + nz.z, a3 = sv.w + nz.w;
            float mloc = fmaxf(fmaxf(a0, a1), fmaxf(a2, a3));
            #pragma unroll
            for (int off = 1; off < 16; off <<= 1)
                mloc = fmaxf(mloc, __shfl_xor_sync(0xffffffffu, mloc, off));
            float m_new = fmaxf(m_run, mloc);
            float al = __expf(m_run - m_new);
            float e0 = __expf(a0 - m_new), e1 = __expf(a1 - m_new);
            float e2 = __expf(a2 - m_new), e3 = __expf(a3 - m_new);
            float ps = (e0 + e1) + (e2 + e3);
            #pragma unroll
            for (int off = 1; off < 16; off <<= 1)
                ps += __shfl_xor_sync(0xffffffffu, ps, off);
            l_run = l_run*al + ps;
            m_run = m_new;
            oA.x *= al; oA.y *= al; oA.z *= al; oA.w *= al;
            oB.x *= al; oB.y *= al; oB.z *= al; oB.w *= al;
            *reinterpret_cast<float4*>(&sS[qi*SSTR + g*4]) = make_float4(e0,e1,e2,e3);
        }
        __syncthreads();
        // ---- V polar roundtrip (reference-exact bins) ----
        polar_tile_exact(v_g + ((size_t)h*T + tt)*D, sTile, sSfx,
                         sTm, sTp, sTn, sLm, sLl, tid);
        // ---- O += P * Vpolar ----
        {
            const float* pr = sS + qi*SSTR;
            const float* vb = sTile + g*4;
            #pragma unroll 4
            for (int t = 0; t < ST; t++) {
                float pv = pr[t];
                float4 va = *reinterpret_cast<const float4*>(vb + t*TSTR);
                float4 vq = *reinterpret_cast<const float4*>(vb + t*TSTR + 64);
                oA.x = fmaf(pv, va.x, oA.x); oA.y = fmaf(pv, va.y, oA.y);
                oA.z = fmaf(pv, va.z, oA.z); oA.w = fmaf(pv, va.w, oA.w);
                oB.x = fmaf(pv, vq.x, oB.x); oB.y = fmaf(pv, vq.y, oB.y);
                oB.z = fmaf(pv, vq.z, oB.z); oB.w = fmaf(pv, vq.w, oB.w);
            }
        }
        __syncthreads();
    }
    // ---- write partials ----
    const size_t pb = (size_t)(h*NC + chunk)*KQ + qi;
    if (g == 0) { g_pm[pb] = m_run; g_pl[pb] = l_run; }
    float* po = g_po + pb*D;
    *reinterpret_cast<float4*>(po + g*4)      = oA;
    *reinterpret_cast<float4*>(po + 64 + g*4) = oB;
}

__global__ void __launch_bounds__(TPB)
combine_kernel(float* __restrict__ out)
{
    const int h  = blockIdx.x;
    const int qi = threadIdx.x >> 4, g = threadIdx.x & 15;
    float M = -CUDART_INF_F;
    #pragma unroll 1
    for (int c = 0; c < NC; c++)
        M = fmaxf(M, g_pm[(h*NC + c)*KQ + qi]);
    float L = 0.0f;
    float4 aA = {0,0,0,0}, aB = {0,0,0,0};
    #pragma unroll 1
    for (int c = 0; c < NC; c++) {
        size_t pb = (size_t)(h*NC + c)*KQ + qi;
        float w = __expf(g_pm[pb] - M);
        L = fmaf(g_pl[pb], w, L);
        const float* po = g_po + pb*D;
        float4 a = *reinterpret_cast<const float4*>(po + g*4);
        float4 b = *reinterpret_cast<const float4*>(po + 64 + g*4);
        aA.x = fmaf(w, a.x, aA.x); aA.y = fmaf(w, a.y, aA.y);
        aA.z = fmaf(w, a.z, aA.z); aA.w = fmaf(w, a.w, aA.w);
        aB.x = fmaf(w, b.x, aB.x); aB.y = fmaf(w, b.y, aB.y);
        aB.z = fmaf(w, b.z, aB.z); aB.w = fmaf(w, b.w, aB.w);
    }
    float inv = __fdiv_rn(1.0f, L);
    float* op = out + ((size_t)(h*KQ + qi))*D;
    aA.x *= inv; aA.y *= inv; aA.z *= inv; aA.w *= inv;
    aB.x *= inv; aB.y *= inv; aB.z *= inv; aB.w *= inv;
    *reinterpret_cast<float4*>(op + g*4)      = aA;
    *reinterpret_cast<float4*>(op + 64 + g*4) = aB;
}

extern "C" void kernel_launch(void* const* d_in, const int* in_sizes, int n_in,
                              void* d_out, int out_size)
{
    const float* q  = (const float*)d_in[0];
    const float* k  = (const float*)d_in[1];
    const float* v  = (const float*)d_in[2];
    const float* nz = (const float*)d_in[3];
    cudaFuncSetAttribute(attn_kernel,
                         cudaFuncAttributeMaxDynamicSharedMemorySize, SMEM_BYTES);
    init_kernel<<<1, 32>>>();
    dim3 grid(NC, H);
    attn_kernel<<<grid, TPB, SMEM_BYTES>>>(q, k, v, nz);
    combine_kernel<<<H, TPB>>>((float*)d_out);
}

// round 17
// speedup vs baseline: 1.8065x; 1.8065x over previous
#include <cuda_runtime.h>
#include <math_constants.h>
#include <cstdint>

#define H    32
#define T    8192
#define KQ   16
#define D    128
#define NC   64          // chunks per head
#define CS   128         // keys per chunk
#define ST   64          // subtile rows held in smem
#define NSUB (CS/ST)
#define TPB  256
#define TSTR 132         // tile row stride (floats)
#define XSTR 133         // suffix row stride (floats)
#define SSTR 68          // score row stride

#define PI_F     3.14159274101257324f   // 0x40490FDB
#define TWO_PI_F 6.28318548202514648f   // 0x40C90FDB

// dynamic smem layout (floats)
#define OFF_Q    0
#define OFF_TILE (OFF_Q + KQ*D)
#define OFF_SFX  (OFF_TILE + ST*TSTR)
#define OFF_S    (OFF_SFX + ST*XSTR)
#define SMEM_FLOATS (OFF_S + KQ*SSTR)
#define SMEM_BYTES  (SMEM_FLOATS*4)

// ---- split-softmax partials ----
__device__ float g_pm[H*NC*KQ];
__device__ float g_pl[H*NC*KQ];
__device__ float g_po[(size_t)H*NC*KQ*D];

// ---- reference-exact quantization tables (filled by init_kernel) ----
__device__ float  d_Tmid[8];
__device__ float  d_Tpos[8];
__device__ float  d_Tneg[8];
__device__ float2 d_lutM[8];
__device__ float2 d_lutL[8];

// Reference acos: StableHLO functional_algorithms real-acos decomposition,
//   acos(x) = atan2(sqrt(fl((1-x))*fl((1+x))), x)
// f32 IEEE intermediates, correctly-rounded f32 atan2 (via double atan2 of
// the exact f32 args, rounded once) — matches CPU-XLA / glibc atan2f.
__device__ __forceinline__ float ref_theta(float c) {
    float a = __fsub_rn(1.0f, c);
    float b = __fadd_rn(1.0f, c);
    float s = __fsqrt_rn(__fmul_rn(a, b));
    return (float)atan2((double)s, (double)c);
}
__device__ __forceinline__ int F_mid(float c) {
    return (int)rintf(__fmul_rn(__fdiv_rn(ref_theta(c), PI_F), 7.0f));
}
__device__ __forceinline__ int F_last(float c, bool neg) {
    float th = ref_theta(c);
    if (neg) th = __fsub_rn(TWO_PI_F, th);
    return (int)rintf(__fmul_rn(__fdiv_rn(th, TWO_PI_F), 7.0f));
}
__device__ __forceinline__ unsigned f2key(float f) {
    unsigned u = __float_as_uint(f);
    return (u & 0x80000000u) ? ~u : (u | 0x80000000u);
}
__device__ __forceinline__ float key2f(unsigned k) {
    return __uint_as_float((k & 0x80000000u) ? (k ^ 0x80000000u) : ~k);
}

// one bisection (or LUT entry) per thread
__global__ void init_kernel() {
    const int tid = threadIdx.x;
    if (blockIdx.x != 0) return;
    const unsigned KLO = f2key(-1.0f), KHI = f2key(1.0f);
    if (tid < 7) {                 // Tmid[1..7], F_mid decreasing
        int k = tid + 1;
        unsigned lo = KLO, hi = KHI;
        while (hi - lo > 1u) {
            unsigned mid = lo + (hi - lo) / 2u;
            if (F_mid(key2f(mid)) >= k) lo = mid; else hi = mid;
        }
        d_Tmid[k] = key2f(lo);
    } else if (tid < 11) {         // Tpos[1..4], F_last(+) decreasing
        int k = tid - 6;
        unsigned lo = KLO, hi = KHI;
        while (hi - lo > 1u) {
            unsigned mid = lo + (hi - lo) / 2u;
            if (F_last(key2f(mid), false) >= k) lo = mid; else hi = mid;
        }
        d_Tpos[k] = key2f(lo);
    } else if (tid < 14) {         // Tneg[5..7], F_last(-) increasing
        int k = tid - 6;
        unsigned lo = KLO, hi = KHI;
        while (hi - lo > 1u) {
            unsigned mid = lo + (hi - lo) / 2u;
            if (F_last(key2f(mid), true) >= k) hi = mid; else lo = mid;
        }
        d_Tneg[k] = key2f(hi);
    } else if (tid >= 16 && tid < 32) {   // LUTs, correctly-rounded sin/cos
        int j = tid - 16;
        if (j < 8) {
            float tM = __fmul_rn(__fdiv_rn((float)j, 7.0f), PI_F);
            d_lutM[j] = make_float2((float)sin((double)tM), (float)cos((double)tM));
        } else {
            int k = j - 8;
            float tL = __fmul_rn(__fdiv_rn((float)k, 7.0f), TWO_PI_F);
            d_lutL[k] = make_float2((float)sin((double)tL), (float)cos((double)tL));
        }
    }
}

// polar roundtrip of ST rows, bit-identical arithmetic to R16, restructured:
//   B1 (tid<ST, serial): tail-first f32 cumsum; cache rn and sign(x[127])
//   B2 (all 256 threads): per-element div/sqrt/clip/bin/LUT  <- the heavy part
//   B3 (tid<ST, serial): sine cumprod + final writes
__device__ __forceinline__ void polar_tile_exact(const float* __restrict__ src,
                                                 float* __restrict__ tile,
                                                 float* __restrict__ sfx,
                                                 float* __restrict__ sRn,
                                                 float* __restrict__ sNeg,
                                                 const float* __restrict__ tm,
                                                 const float* __restrict__ tp,
                                                 const float* __restrict__ tn,
                                                 const float2* __restrict__ lm,
                                                 const float2* __restrict__ ll,
                                                 int tid)
{
    for (int i = tid; i < ST*32; i += TPB) {
        int row = i >> 5, col = i & 31;
        reinterpret_cast<float4*>(tile + row*TSTR)[col] =
            reinterpret_cast<const float4*>(src + (size_t)row*D)[col];
    }
    __syncthreads();
    // B1: sequential suffix cumsum (reference association)
    if (tid < ST) {
        const float* xr = tile + tid*TSTR;
        float* sr = sfx + tid*XSTR;
        float s = 0.0f;
        #pragma unroll 4
        for (int i = 127; i >= 0; --i) {
            float x = xr[i];
            s = __fadd_rn(s, __fmul_rn(x, x));
            sr[i] = s;
        }
        sRn[tid]  = __fsqrt_rn(s);
        sNeg[tid] = (xr[127] < 0.0f) ? 1.0f : 0.0f;
    }
    __syncthreads();
    // B2: element-parallel quantize + dequant LUT (sn -> sfx slot, cs -> tile slot)
    for (int e = tid; e < ST*128; e += TPB) {
        const int row = e >> 7, i = e & 127;
        float* xs = tile + row*TSTR + i;
        float* ss = sfx  + row*XSTR + i;
        float sn, cs;
        if (i == 127) {
            sn = 1.0f; cs = 1.0f;
        } else {
            float c = __fdiv_rn(*xs, fmaxf(__fsqrt_rn(*ss), 1e-12f));
            c = fminf(1.0f, fmaxf(-1.0f, c));
            if (i < 126) {
                int idx = (int)(c <= tm[1]) + (int)(c <= tm[2]) + (int)(c <= tm[3])
                        + (int)(c <= tm[4]) + (int)(c <= tm[5]) + (int)(c <= tm[6])
                        + (int)(c <= tm[7]);
                float2 sc = lm[idx];
                sn = sc.x; cs = sc.y;
            } else {   // i == 126: last angle, range 2*pi, sign from x[127]
                int idx;
                if (sNeg[row] != 0.0f)
                    idx = 4 + (int)(c >= tn[5]) + (int)(c >= tn[6]) + (int)(c >= tn[7]);
                else
                    idx = (int)(c <= tp[1]) + (int)(c <= tp[2])
                        + (int)(c <= tp[3]) + (int)(c <= tp[4]);
                float2 sc = ll[idx];
                sn = sc.x; cs = sc.y;
            }
        }
        *ss = sn;
        *xs = cs;
    }
    __syncthreads();
    // B3: sequential sine cumprod + final values (same mul order as R16)
    if (tid < ST) {
        float* xr = tile + tid*TSTR;
        const float* sr = sfx + tid*XSTR;
        const float rn = sRn[tid];
        float cp = 1.0f;
        #pragma unroll 4
        for (int i = 0; i < 128; ++i) {
            float cs = xr[i];
            float sn = sr[i];
            xr[i] = __fmul_rn(__fmul_rn(rn, cp), cs);
            cp = __fmul_rn(cp, sn);
        }
    }
    __syncthreads();
}

__global__ void __launch_bounds__(TPB)
attn_kernel(const float* __restrict__ q_g,
            const float* __restrict__ k_g,
            const float* __restrict__ v_g,
            const float* __restrict__ nz_g)
{
    extern __shared__ float sm[];
    float*  sQ    = sm + OFF_Q;
    float*  sTile = sm + OFF_TILE;
    float*  sSfx  = sm + OFF_SFX;
    float*  sS    = sm + OFF_S;
    __shared__ float  sTm[8], sTp[8], sTn[8];
    __shared__ float2 sLm[8], sLl[8];
    __shared__ float  sRn[ST], sNeg[ST];

    const int chunk = blockIdx.x;
    const int h     = blockIdx.y;
    const int tid   = threadIdx.x;
    const int qi    = tid >> 4, g = tid & 15;
    const float inv_sqrt_d = __fdiv_rn(1.0f, __fsqrt_rn(128.0f));

    if (tid < 8) {
        sTm[tid] = d_Tmid[tid]; sTp[tid] = d_Tpos[tid]; sTn[tid] = d_Tneg[tid];
        sLm[tid] = d_lutM[tid]; sLl[tid] = d_lutL[tid];
    }
    {
        const float4* qh = reinterpret_cast<const float4*>(q_g + (size_t)h*KQ*D);
        #pragma unroll
        for (int i = tid; i < KQ*D/4; i += TPB)
            reinterpret_cast<float4*>(sQ)[i] = qh[i];
    }
    __syncthreads();

    const int t0 = chunk * CS;
    float m_run = -CUDART_INF_F, l_run = 0.0f;
    float4 oA = {0,0,0,0}, oB = {0,0,0,0};

    #pragma unroll 1
    for (int sub = 0; sub < NSUB; ++sub) {
        const int tt = t0 + sub*ST;
        // ---- K polar roundtrip (reference-exact bins) ----
        polar_tile_exact(k_g + ((size_t)h*T + tt)*D, sTile, sSfx, sRn, sNeg,
                         sTm, sTp, sTn, sLm, sLl, tid);
        // ---- scores S[16 x 64] ----
        {
            const int lane = tid & 31, wid = tid >> 5;
            const int key = lane & 7, dg = lane >> 3;
            float acc[KQ];
            #pragma unroll
            for (int i = 0; i < KQ; i++) acc[i] = 0.0f;
            const float* kr = sTile + (wid*8 + key)*TSTR + dg*32;
            const float* qb = sQ + dg*32;
            #pragma unroll
            for (int j = 0; j < 8; j++) {
                float4 kv = reinterpret_cast<const float4*>(kr)[j];
                #pragma unroll
                for (int q = 0; q < KQ; q++) {
                    float4 qv = reinterpret_cast<const float4*>(qb + q*D)[j];
                    acc[q] = fmaf(kv.x, qv.x, fmaf(kv.y, qv.y,
                             fmaf(kv.z, qv.z, fmaf(kv.w, qv.w, acc[q]))));
                }
            }
            #pragma unroll
            for (int q = 0; q < KQ; q++) {
                acc[q] += __shfl_xor_sync(0xffffffffu, acc[q], 8);
                acc[q] += __shfl_xor_sync(0xffffffffu, acc[q], 16);
            }
            #pragma unroll
            for (int qq = 0; qq < 4; qq++) {
                int q = dg*4 + qq;
                sS[q*SSTR + wid*8 + key] = __fmul_rn(acc[q], inv_sqrt_d);
            }
        }
        __syncthreads();
        // ---- online softmax update (adds noise) ----
        {
            float4 sv = *reinterpret_cast<const float4*>(&sS[qi*SSTR + g*4]);
            float4 nz = reinterpret_cast<const float4*>(
                            nz_g + ((size_t)(h*KQ + qi))*T + tt)[g];
            float a0 = sv.x + nz.x, a1 = sv.y + nz.y;
            float a2 = sv.z + nz.z, a3 = sv.w + nz.w;
            float mloc = fmaxf(fmaxf(a0, a1), fmaxf(a2, a3));
            #pragma unroll
            for (int off = 1; off < 16; off <<= 1)
                mloc = fmaxf(mloc, __shfl_xor_sync(0xffffffffu, mloc, off));
            float m_new = fmaxf(m_run, mloc);
            float al = __expf(m_run - m_new);
            float e0 = __expf(a0 - m_new), e1 = __expf(a1 - m_new);
            float e2 = __expf(a2 - m_new), e3 = __expf(a3 - m_new);
            float ps = (e0 + e1) + (e2 + e3);
            #pragma unroll
            for (int off = 1; off < 16; off <<= 1)
                ps += __shfl_xor_sync(0xffffffffu, ps, off);
            l_run = l_run*al + ps;
            m_run = m_new;
            oA.x *= al; oA.y *= al; oA.z *= al; oA.w *= al;
            oB.x *= al; oB.y *= al; oB.z *= al; oB.w *= al;
            *reinterpret_cast<float4*>(&sS[qi*SSTR + g*4]) = make_float4(e0,e1,e2,e3);
        }
        __syncthreads();
        // ---- V polar roundtrip (reference-exact bins) ----
        polar_tile_exact(v_g + ((size_t)h*T + tt)*D, sTile, sSfx, sRn, sNeg,
                         sTm, sTp, sTn, sLm, sLl, tid);
        // ---- O += P * Vpolar ----
        {
            const float* pr = sS + qi*SSTR;
            const float* vb = sTile + g*4;
            #pragma unroll 4
            for (int t = 0; t < ST; t++) {
                float pv = pr[t];
                float4 va = *reinterpret_cast<const float4*>(vb + t*TSTR);
                float4 vq = *reinterpret_cast<const float4*>(vb + t*TSTR + 64);
                oA.x = fmaf(pv, va.x, oA.x); oA.y = fmaf(pv, va.y, oA.y);
                oA.z = fmaf(pv, va.z, oA.z); oA.w = fmaf(pv, va.w, oA.w);
                oB.x = fmaf(pv, vq.x, oB.x); oB.y = fmaf(pv, vq.y, oB.y);
                oB.z = fmaf(pv, vq.z, oB.z); oB.w = fmaf(pv, vq.w, oB.w);
            }
        }
        __syncthreads();
    }
    // ---- write partials ----
    const size_t pb = (size_t)(h*NC + chunk)*KQ + qi;
    if (g == 0) { g_pm[pb] = m_run; g_pl[pb] = l_run; }
    float* po = g_po + pb*D;
    *reinterpret_cast<float4*>(po + g*4)      = oA;
    *reinterpret_cast<float4*>(po + 64 + g*4) = oB;
}

__global__ void __launch_bounds__(TPB)
combine_kernel(float* __restrict__ out)
{
    const int h  = blockIdx.x;
    const int qi = threadIdx.x >> 4, g = threadIdx.x & 15;
    float M = -CUDART_INF_F;
    #pragma unroll 1
    for (int c = 0; c < NC; c++)
        M = fmaxf(M, g_pm[(h*NC + c)*KQ + qi]);
    float L = 0.0f;
    float4 aA = {0,0,0,0}, aB = {0,0,0,0};
    #pragma unroll 1
    for (int c = 0; c < NC; c++) {
        size_t pb = (size_t)(h*NC + c)*KQ + qi;
        float w = __expf(g_pm[pb] - M);
        L = fmaf(g_pl[pb], w, L);
        const float* po = g_po + pb*D;
        float4 a = *reinterpret_cast<const float4*>(po + g*4);
        float4 b = *reinterpret_cast<const float4*>(po + 64 + g*4);
        aA.x = fmaf(w, a.x, aA.x); aA.y = fmaf(w, a.y, aA.y);
        aA.z = fmaf(w, a.z, aA.z); aA.w = fmaf(w, a.w, aA.w);
        aB.x = fmaf(w, b.x, aB.x); aB.y = fmaf(w, b.y, aB.y);
        aB.z = fmaf(w, b.z, aB.z); aB.w = fmaf(w, b.w, aB.w);
    }
    float inv = __fdiv_rn(1.0f, L);
    float* op = out + ((size_t)(h*KQ + qi))*D;
    aA.x *= inv; aA.y *= inv; aA.z *= inv; aA.w *= inv;
    aB.x *= inv; aB.y *= inv; aB.z *= inv; aB.w *= inv;
    *reinterpret_cast<float4*>(op + g*4)      = aA;
    *reinterpret_cast<float4*>(op + 64 + g*4) = aB;
}

extern "C" void kernel_launch(void* const* d_in, const int* in_sizes, int n_in,
                              void* d_out, int out_size)
{
    const float* q  = (const float*)d_in[0];
    const float* k  = (const float*)d_in[1];
    const float* v  = (const float*)d_in[2];
    const float* nz = (const float*)d_in[3];
    cudaFuncSetAttribute(attn_kernel,
                         cudaFuncAttributeMaxDynamicSharedMemorySize, SMEM_BYTES);
    init_kernel<<<1, 32>>>();
    dim3 grid(NC, H);
    attn_kernel<<<grid, TPB, SMEM_BYTES>>>(q, k, v, nz);
    combine_kernel<<<H, TPB>>>((float*)d_out);
}